// round 15
// baseline (speedup 1.0000x reference)
#include <cuda_runtime.h>

#define BATCH 2048
#define CELL 512
#define KDIM 30
#define LPAD 1024
#define VDIM 80

// scratch: [B, 90] = alpha | beta | kappa (kappa pre-summed with kappa_old)
__device__ float g_params[BATCH * 3 * KDIM];

// ---------------------------------------------------------------------------
// Kernel A: params = exp(x @ W.T + b).  4-outputs x 8-batches register tile
// per warp under launch_bounds(256,2) (the config r14 proved grants the full
// 128-reg budget; r13's failure was the (512)+no-min-blocks 64-reg trap).
// Per j-step: 4 W float4 + 8 x float4 loads feed 128 lane-FMAs -> smem
// crossbar traffic / 4 vs r14.  Four r11-proven 9-shfl folds reduce the
// 32 accumulators; lane 4g ends holding batch g for each output group.
// ---------------------------------------------------------------------------
__global__ __launch_bounds__(256, 2) void params_kernel(
    const float* __restrict__ x,          // [B, CELL]
    const float* __restrict__ kappa_old,  // [B, K]
    const float* __restrict__ W,          // [3K, CELL]
    const float* __restrict__ bias,       // [3K]
    float* __restrict__ out_kappa)        // [B, K]
{
    __shared__ float4 xs[8][CELL / 4 + 1];   // 16.5 KB, rows bank-shifted
    __shared__ float s_bias[3 * KDIM];

    const int tid = threadIdx.x;
    const int wid = tid >> 5;                // 8 warps
    const int lane = tid & 31;
    const int b0 = blockIdx.x * 8;

    const float4* xg = (const float4*)(x + (size_t)b0 * CELL);
    for (int i = tid; i < 8 * CELL / 4; i += 256) {
        int r = i >> 7;
        int j = i & 127;
        xs[r][j] = xg[r * 128 + j];
    }
    if (tid < 3 * KDIM) s_bias[tid] = bias[tid];
    __syncthreads();

    // 23 output-quads over 8 warps (quad 22 = outputs 88..91; 90/91 guarded)
    for (int q = wid; q < 23; q += 8) {
        const int o0 = 4 * q;
        const float4* w0 = (const float4*)(W + (size_t)min(o0 + 0, 89) * CELL);
        const float4* w1 = (const float4*)(W + (size_t)min(o0 + 1, 89) * CELL);
        const float4* w2 = (const float4*)(W + (size_t)min(o0 + 2, 89) * CELL);
        const float4* w3 = (const float4*)(W + (size_t)min(o0 + 3, 89) * CELL);

        float a0[8], a1[8], a2[8], a3[8];
        #pragma unroll
        for (int r = 0; r < 8; r++) { a0[r] = 0.f; a1[r] = 0.f; a2[r] = 0.f; a3[r] = 0.f; }

        #pragma unroll
        for (int j = 0; j < 4; j++) {
            const int idx = lane + 32 * j;
            float4 wv0 = w0[idx];
            float4 wv1 = w1[idx];
            float4 wv2 = w2[idx];
            float4 wv3 = w3[idx];
            #pragma unroll
            for (int b = 0; b < 8; b++) {
                float4 xv = xs[b][idx];
                a0[b] = fmaf(wv0.x, xv.x, fmaf(wv0.y, xv.y,
                        fmaf(wv0.z, xv.z, fmaf(wv0.w, xv.w, a0[b]))));
                a1[b] = fmaf(wv1.x, xv.x, fmaf(wv1.y, xv.y,
                        fmaf(wv1.z, xv.z, fmaf(wv1.w, xv.w, a1[b]))));
                a2[b] = fmaf(wv2.x, xv.x, fmaf(wv2.y, xv.y,
                        fmaf(wv2.z, xv.z, fmaf(wv2.w, xv.w, a2[b]))));
                a3[b] = fmaf(wv3.x, xv.x, fmaf(wv3.y, xv.y,
                        fmaf(wv3.z, xv.z, fmaf(wv3.w, xv.w, a3[b]))));
            }
        }

        // r11 9-shfl merged fold, applied per output group.
        // After each fold, lane 4g holds that group's total for batch g.
        #define FOLD9(A)                                                      \
        {                                                                     \
            _Pragma("unroll")                                                 \
            for (int r = 0; r < 4; r++) {                                     \
                float send = (lane & 16) ? A[r] : A[r + 4];                   \
                float recv = __shfl_xor_sync(0xffffffffu, send, 16);          \
                A[r] = ((lane & 16) ? A[r + 4] : A[r]) + recv;                \
            }                                                                 \
            _Pragma("unroll")                                                 \
            for (int r = 0; r < 2; r++) {                                     \
                float send = (lane & 8) ? A[r] : A[r + 2];                    \
                float recv = __shfl_xor_sync(0xffffffffu, send, 8);           \
                A[r] = ((lane & 8) ? A[r + 2] : A[r]) + recv;                 \
            }                                                                 \
            {                                                                 \
                float send = (lane & 4) ? A[0] : A[1];                        \
                float recv = __shfl_xor_sync(0xffffffffu, send, 4);           \
                A[0] = ((lane & 4) ? A[1] : A[0]) + recv;                     \
            }                                                                 \
            A[0] += __shfl_xor_sync(0xffffffffu, A[0], 2);                    \
            A[0] += __shfl_xor_sync(0xffffffffu, A[0], 1);                    \
        }
        FOLD9(a0)
        FOLD9(a1)
        FOLD9(a2)
        FOLD9(a3)
        #undef FOLD9

        if ((lane & 3) == 0) {
            const int g = lane >> 2;          // batch index within block
            const int b = b0 + g;
            float v[4] = {a0[0], a1[0], a2[0], a3[0]};
            #pragma unroll
            for (int s = 0; s < 4; s++) {
                const int o = o0 + s;
                if (o < 3 * KDIM) {
                    float p = __expf(v[s] + s_bias[o]);
                    if (o >= 2 * KDIM) {
                        int k = o - 2 * KDIM;
                        p += kappa_old[(size_t)b * KDIM + k];
                        out_kappa[(size_t)b * KDIM + k] = p;
                    }
                    g_params[(size_t)b * (3 * KDIM) + o] = p;
                }
            }
        }
    }
}

// ---------------------------------------------------------------------------
// Kernel B: sparse phi.  One block per batch; Gaussian k only touched where
// beta*(kappa-l)^2 < 92 (expf underflow -> 0, matching fp32 reference).
// ---------------------------------------------------------------------------
__global__ __launch_bounds__(256) void phi_kernel(
    const float* __restrict__ text_lens,  // [B, 1]
    float* __restrict__ out_phi)          // [B, L+1]
{
    __shared__ float s_par[3 * KDIM];
    __shared__ float s_phi[LPAD + 1];

    const int bid = blockIdx.x;
    const int tid = threadIdx.x;
    const int wid = tid >> 5;
    const int lane = tid & 31;

    if (tid < 3 * KDIM)
        s_par[tid] = g_params[(size_t)bid * (3 * KDIM) + tid];
    #pragma unroll
    for (int l = tid; l <= LPAD; l += 256)
        s_phi[l] = 0.0f;
    __syncthreads();

    for (int k = wid; k < KDIM; k += 8) {
        const float alpha = s_par[k];
        const float beta  = s_par[KDIM + k];
        const float kap   = s_par[2 * KDIM + k];
        const float r = fminf(sqrtf(92.0f / beta), 1100.0f);
        const int lo = max(0, (int)(kap - r));
        const int hi = min(LPAD, (int)(kap + r) + 1);
        for (int l = lo + lane; l <= hi; l += 32) {
            float d = kap - (float)l;
            atomicAdd(&s_phi[l], alpha * __expf(-beta * d * d));
        }
    }
    __syncthreads();

    const float scale = (float)LPAD / text_lens[bid];
    for (int l = tid; l <= LPAD; l += 256)
        out_phi[(size_t)bid * (LPAD + 1) + l] = s_phi[l] * scale;
}

// ---------------------------------------------------------------------------
// Kernel C: streaming w reduction — EXACT measured-best config (grid 2048,
// block 256, ~118us @ 73% DRAM = device ceiling for this pattern). FROZEN.
// ---------------------------------------------------------------------------
__global__ __launch_bounds__(256) void wsum_kernel(
    const float4* __restrict__ onehots,   // [B, L*V/4]
    const float* __restrict__ phi,        // [B, L+1]
    float* __restrict__ out_w)            // [B, V]
{
    __shared__ float s_phi[LPAD];
    __shared__ float s_w[VDIM];

    const int bid = blockIdx.x;
    const int tid = threadIdx.x;

    #pragma unroll
    for (int i = tid; i < LPAD; i += 256)
        s_phi[i] = phi[(size_t)bid * (LPAD + 1) + i];
    if (tid < VDIM) s_w[tid] = 0.0f;
    __syncthreads();

    const float4* oh = onehots + (size_t)bid * (LPAD * VDIM / 4);

    float4 acc[5];
    int l0[5], cb[5];
    #pragma unroll
    for (int m = 0; m < 5; m++) {
        int e0 = 4 * tid + 1024 * m;
        l0[m] = e0 / VDIM;
        cb[m] = e0 % VDIM;
        acc[m] = make_float4(0.f, 0.f, 0.f, 0.f);
    }

    #pragma unroll 2
    for (int g = 0; g < 16; g++) {
        #pragma unroll
        for (int m = 0; m < 5; m++) {
            float4 v4 = __ldcs(&oh[tid + 256 * (m + 5 * g)]);
            float ph = s_phi[l0[m] + 64 * g];
            acc[m].x = fmaf(ph, v4.x, acc[m].x);
            acc[m].y = fmaf(ph, v4.y, acc[m].y);
            acc[m].z = fmaf(ph, v4.z, acc[m].z);
            acc[m].w = fmaf(ph, v4.w, acc[m].w);
        }
    }
    __syncthreads();

    #pragma unroll
    for (int m = 0; m < 5; m++) {
        atomicAdd(&s_w[cb[m] + 0], acc[m].x);
        atomicAdd(&s_w[cb[m] + 1], acc[m].y);
        atomicAdd(&s_w[cb[m] + 2], acc[m].z);
        atomicAdd(&s_w[cb[m] + 3], acc[m].w);
    }
    __syncthreads();

    if (tid < VDIM) out_w[(size_t)bid * VDIM + tid] = s_w[tid];
}

extern "C" void kernel_launch(void* const* d_in, const int* in_sizes, int n_in,
                              void* d_out, int out_size) {
    const float* x         = (const float*)d_in[0];
    const float* kappa_old = (const float*)d_in[1];
    const float4* onehots  = (const float4*)d_in[2];
    const float* text_lens = (const float*)d_in[3];
    const float* W         = (const float*)d_in[4];
    const float* bias      = (const float*)d_in[5];

    float* out = (float*)d_out;
    float* out_w     = out;                                  // [B, V]
    float* out_kappa = out + (size_t)BATCH * VDIM;           // [B, K]
    float* out_phi   = out + (size_t)BATCH * (VDIM + KDIM);  // [B, L+1]

    params_kernel<<<BATCH / 8, 256>>>(x, kappa_old, W, bias, out_kappa);
    phi_kernel<<<BATCH, 256>>>(text_lens, out_phi);
    wsum_kernel<<<BATCH, 256>>>(onehots, out_phi, out_w);
}